// round 10
// baseline (speedup 1.0000x reference)
#include <cuda_runtime.h>
#include <cuda_bf16.h>
#include <cstdint>

#define NN   50000
#define EE   800000
#define INF  128
#define HF   128
#define RR   8
#define OUTF 2
#define BN_EPS 1e-5f
#define GEMM_TILES ((NN + 127) / 128)   // 391
#define BINS (RR * NN)                  // 400000 (type,src) bins
#define SCAN_BLOCKS ((BINS + 1023) / 1024)  // 391

// ---------------- scratch (device globals; no allocation allowed) ----------
__device__ float g_agg[(size_t)NN * HF];            // layer accumulator
__device__ __nv_bfloat16 g_xhi[(size_t)NN * HF];    // bf16 hi split of acts
__device__ __nv_bfloat16 g_xlo[(size_t)NN * HF];    // bf16 lo split
__device__ __nv_bfloat16 g_whi[9 * 128 * 128];      // [mat][n][k] W^T, hi
__device__ __nv_bfloat16 g_wlo[9 * 128 * 128];      // lo
__device__ int   g_deg[NN * RR];
__device__ float g_invdeg[NN * RR];
__device__ float g_sum[HF];
__device__ float g_sumsq[HF];
// edge sorting by (type, src)
__device__ int   g_hist[BINS];      // per-bin counts
__device__ int   g_hcur[BINS];      // scan result -> cursors (end after place)
__device__ int   g_bsum[SCAN_BLOCKS];
__device__ int   g_etgt[EE];        // targets, sorted by (type, src)

// ======================= small helpers ======================================
__device__ __forceinline__ uint32_t smem_to_u32(const void* p) {
    uint32_t a;
    asm("{ .reg .u64 t; cvta.to.shared.u64 t, %1; cvt.u32.u64 %0, t; }"
        : "=r"(a) : "l"(p));
    return a;
}
__device__ __forceinline__ void cp16(uint32_t dst, const void* src) {
    asm volatile("cp.async.cg.shared.global [%0], [%1], 16;"
                 :: "r"(dst), "l"(__cvta_generic_to_global(src)));
}
__device__ __forceinline__ void mma_bf16(float d[4], const uint32_t a[4],
                                         uint32_t b0, uint32_t b1) {
    asm volatile(
        "mma.sync.aligned.m16n8k16.row.col.f32.bf16.bf16.f32 "
        "{%0,%1,%2,%3}, {%4,%5,%6,%7}, {%8,%9}, {%0,%1,%2,%3};"
        : "+f"(d[0]), "+f"(d[1]), "+f"(d[2]), "+f"(d[3])
        : "r"(a[0]), "r"(a[1]), "r"(a[2]), "r"(a[3]), "r"(b0), "r"(b1));
}
__device__ __forceinline__ void ldsm_x4(uint32_t r[4], uint32_t addr) {
    asm volatile("ldmatrix.sync.aligned.m8n8.x4.shared.b16 {%0,%1,%2,%3}, [%4];"
        : "=r"(r[0]), "=r"(r[1]), "=r"(r[2]), "=r"(r[3]) : "r"(addr));
}

// =============== SMEM layout (u32 units), stride 68 u32 = 136 bf16 ==========
#define SWU    68
#define ROWB   (SWU * 4)                   // 272 bytes per row
#define AH_U   0
#define AL_U   (128 * SWU)                 // 8704
#define B0_U   (2 * 128 * SWU)             // 17408
#define B1_U   (B0_U + 128 * SWU)          // 26112
#define SMEM_U32S   (B1_U + 128 * SWU)     // 34816
#define SMEM_BYTES  (SMEM_U32S * 4)        // 139264
// f32 stage tile (reuses B0+B1 region after MMA passes): 128 x (stride 132)
#define STG_STRIDE 132                     // 128*132*4 = 67584 <= 69632

// prefetch one 128x128 bf16 tile (row-major [n][k]) into padded smem
__device__ __forceinline__ void prefetch_B(uint32_t sb, int bofs_u,
                                           const __nv_bfloat16* W) {
    int tid = threadIdx.x;
#pragma unroll
    for (int i = 0; i < 8; i++) {
        int e = i * 256 + tid;            // 0..2047 uint4s
        int row = e >> 4;                 // 0..127
        int q   = e & 15;                 // uint4 (8 bf16) within row
        cp16(sb + (uint32_t)(bofs_u + row * SWU + q * 4) * 4, W + row * 128 + q * 8);
    }
}

// one bf16 pass via ldmatrix: D += A x B^T over K=128.
__device__ __forceinline__ void do_pass(uint32_t aBase, uint32_t bBase,
                                        uint32_t aLane, uint32_t bLane,
                                        float d[4][4][4]) {
#pragma unroll
    for (int ks = 0; ks < 8; ks++) {
        uint32_t kb = (uint32_t)ks * 32;          // 16 bf16 = 32 bytes
        uint32_t a[4][4];
#pragma unroll
        for (int mt = 0; mt < 4; mt++)
            ldsm_x4(a[mt], aBase + aLane + (uint32_t)(mt * 16) * ROWB + kb);
#pragma unroll
        for (int p = 0; p < 2; p++) {
            uint32_t b[4];
            ldsm_x4(b, bBase + bLane + (uint32_t)(p * 16) * ROWB + kb);
#pragma unroll
            for (int mt = 0; mt < 4; mt++) {
                mma_bf16(d[mt][2 * p],     a[mt], b[0], b[1]);
                mma_bf16(d[mt][2 * p + 1], a[mt], b[2], b[3]);
            }
        }
    }
}

// load A hi/lo tiles into smem (rows m0..m0+127, zero-padded past NN)
__device__ __forceinline__ void load_A(uint32_t sb, uint32_t* smu, int m0) {
    int tid = threadIdx.x;
#pragma unroll
    for (int i = 0; i < 8; i++) {
        int e = i * 256 + tid;
        int row = e >> 4, q = e & 15;
        uint32_t dh = sb + (uint32_t)(AH_U + row * SWU + q * 4) * 4;
        uint32_t dl = sb + (uint32_t)(AL_U + row * SWU + q * 4) * 4;
        if (m0 + row < NN) {
            cp16(dh, g_xhi + (size_t)(m0 + row) * 128 + q * 8);
            cp16(dl, g_xlo + (size_t)(m0 + row) * 128 + q * 8);
        } else {
            uint4 z = make_uint4(0, 0, 0, 0);
            *reinterpret_cast<uint4*>(smu + AH_U + row * SWU + q * 4) = z;
            *reinterpret_cast<uint4*>(smu + AL_U + row * SWU + q * 4) = z;
        }
    }
}

// ============ root GEMM: agg = x @ root + bias (mat index 8) ================
__global__ void __launch_bounds__(256, 1) root_gemm_kernel(const float* __restrict__ bias) {
    extern __shared__ uint32_t smu[];
    uint32_t sb = smem_to_u32(smu);
    const int tid = threadIdx.x;
    const int wid = tid >> 5, lane = tid & 31;
    const int wm = wid & 1, wn = wid >> 1;
    const int lr = lane >> 2, lc = lane & 3;
    const int m0 = blockIdx.x * 128;

    const uint32_t aLane = (uint32_t)(wm * 64 + (lane & 15)) * ROWB
                         + (uint32_t)(lane >> 4) * 16;
    const uint32_t bLane = (uint32_t)(wn * 32 + ((lane >> 4) & 1) * 8 + (lane & 7)) * ROWB
                         + (uint32_t)((lane >> 3) & 1) * 16;

    load_A(sb, smu, m0);
    prefetch_B(sb, B0_U, g_whi + 8 * 16384);
    prefetch_B(sb, B1_U, g_wlo + 8 * 16384);
    asm volatile("cp.async.commit_group;" ::: "memory");
    asm volatile("cp.async.wait_group 0;" ::: "memory");
    __syncthreads();

    float d[4][4][4];
#pragma unroll
    for (int mt = 0; mt < 4; mt++)
#pragma unroll
        for (int nt = 0; nt < 4; nt++)
#pragma unroll
            for (int j = 0; j < 4; j++) d[mt][nt][j] = 0.f;

    const uint32_t ahB = sb + AH_U * 4, alB = sb + AL_U * 4;
    const uint32_t bhB = sb + B0_U * 4, blB = sb + B1_U * 4;
    do_pass(ahB, bhB, aLane, bLane, d);
    do_pass(alB, bhB, aLane, bLane, d);
    do_pass(ahB, blB, aLane, bLane, d);

#pragma unroll
    for (int mt = 0; mt < 4; mt++) {
        int r0 = m0 + wm * 64 + mt * 16 + lr;
#pragma unroll
        for (int nt = 0; nt < 4; nt++) {
            int col = wn * 32 + nt * 8 + lc * 2;
            float b0 = bias[col], b1 = bias[col + 1];
            if (r0 < NN)
                *reinterpret_cast<float2*>(g_agg + (size_t)r0 * HF + col) =
                    make_float2(d[mt][nt][0] + b0, d[mt][nt][1] + b1);
            if (r0 + 8 < NN)
                *reinterpret_cast<float2*>(g_agg + (size_t)(r0 + 8) * HF + col) =
                    make_float2(d[mt][nt][2] + b0, d[mt][nt][3] + b1);
        }
    }
}

// ====== fused GEMM+scatter: for mats 0..7, compute tile then red into agg ===
// Edges sorted by (type, src): bins [mat*NN+m0, mat*NN+m0+128) belong to this
// CTA. Tile staged in SMEM (dead B buffers); no global xw buffer exists.
__global__ void __launch_bounds__(256, 1) gemm_scatter_kernel() {
    extern __shared__ uint32_t smu[];
    uint32_t sb = smem_to_u32(smu);
    const int tid = threadIdx.x;
    const int wid = tid >> 5, lane = tid & 31;
    const int wm = wid & 1, wn = wid >> 1;
    const int lr = lane >> 2, lc = lane & 3;
    const int m0 = blockIdx.x * 128;

    const uint32_t aLane = (uint32_t)(wm * 64 + (lane & 15)) * ROWB
                         + (uint32_t)(lane >> 4) * 16;
    const uint32_t bLane = (uint32_t)(wn * 32 + ((lane >> 4) & 1) * 8 + (lane & 7)) * ROWB
                         + (uint32_t)((lane >> 3) & 1) * 16;

    load_A(sb, smu, m0);
    asm volatile("cp.async.commit_group;" ::: "memory");
    asm volatile("cp.async.wait_group 0;" ::: "memory");
    __syncthreads();

    const uint32_t ahB = sb + AH_U * 4, alB = sb + AL_U * 4;
    const uint32_t bhB = sb + B0_U * 4, blB = sb + B1_U * 4;
    float* st = reinterpret_cast<float*>(smu + B0_U);

    float d[4][4][4];
#pragma unroll
    for (int mt = 0; mt < 4; mt++)
#pragma unroll
        for (int nt = 0; nt < 4; nt++)
#pragma unroll
            for (int j = 0; j < 4; j++) d[mt][nt][j] = 0.f;

    for (int mat = 0; mat < 8; mat++) {
        // B tiles for this mat (stage region is free again here)
        prefetch_B(sb, B0_U, g_whi + mat * 16384);
        prefetch_B(sb, B1_U, g_wlo + mat * 16384);
        asm volatile("cp.async.commit_group;" ::: "memory");
        asm volatile("cp.async.wait_group 0;" ::: "memory");
        __syncthreads();

        do_pass(ahB, bhB, aLane, bLane, d);   // hi*hi
        do_pass(alB, bhB, aLane, bLane, d);   // lo*hi
        do_pass(ahB, blB, aLane, bLane, d);   // hi*lo
        __syncthreads();                      // all B reads done

        // stage tile as f32 (overwrites B buffers), reset accumulators
#pragma unroll
        for (int mt = 0; mt < 4; mt++) {
            int row0 = wm * 64 + mt * 16 + lr;
#pragma unroll
            for (int nt = 0; nt < 4; nt++) {
                int col = wn * 32 + nt * 8 + lc * 2;
                st[row0 * STG_STRIDE + col]           = d[mt][nt][0];
                st[row0 * STG_STRIDE + col + 1]       = d[mt][nt][1];
                st[(row0 + 8) * STG_STRIDE + col]     = d[mt][nt][2];
                st[(row0 + 8) * STG_STRIDE + col + 1] = d[mt][nt][3];
#pragma unroll
                for (int j = 0; j < 4; j++) d[mt][nt][j] = 0.f;
            }
        }
        __syncthreads();

        // scatter: warp wid owns rows wid*16 .. wid*16+15
        for (int rr = 0; rr < 16; rr++) {
            int row  = wid * 16 + rr;
            int grow = m0 + row;
            if (grow >= NN) break;
            int bin = mat * NN + grow;
            int cnt = g_hist[bin];
            if (cnt == 0) continue;
            int end = g_hcur[bin], start = end - cnt;
            float4 v = *reinterpret_cast<const float4*>(
                st + row * STG_STRIDE + lane * 4);
            for (int i = start; i < end; i++) {
                int tgt = __ldg(&g_etgt[i]);
                float inv = __ldg(&g_invdeg[tgt * RR + mat]);
                float* dst = g_agg + (size_t)tgt * HF + lane * 4;
                asm volatile("red.global.add.v4.f32 [%0], {%1, %2, %3, %4};"
                    :: "l"(__cvta_generic_to_global(dst)),
                       "f"(v.x * inv), "f"(v.y * inv), "f"(v.z * inv), "f"(v.w * inv)
                    : "memory");
            }
        }
        __syncthreads();   // stage reads done before next B prefetch
    }
}

// ======================= prep kernels ========================================
__global__ void split_x_kernel(const float* __restrict__ x_in) {
    size_t idx = (size_t)blockIdx.x * blockDim.x + threadIdx.x;
    if (idx >= (size_t)NN * HF) return;
    float v = x_in[idx];
    __nv_bfloat16 h = __float2bfloat16_rn(v);
    g_xhi[idx] = h;
    g_xlo[idx] = __float2bfloat16_rn(v - __bfloat162float(h));
}

// transpose W[mat][k][n] -> [mat][n][k], split hi/lo bf16. mat 8 = root.
__global__ void split_w_kernel(const float* __restrict__ w, const float* __restrict__ root) {
    int idx = blockIdx.x * blockDim.x + threadIdx.x;
    if (idx >= 9 * 16384) return;
    int mat = idx >> 14;
    int n = (idx >> 7) & 127;
    int k = idx & 127;
    float v = (mat < 8) ? w[(mat << 14) + (k << 7) + n] : root[(k << 7) + n];
    __nv_bfloat16 h = __float2bfloat16_rn(v);
    g_whi[idx] = h;
    g_wlo[idx] = __float2bfloat16_rn(v - __bfloat162float(h));
}

__global__ void zero_prep_kernel() {
    int idx = blockIdx.x * blockDim.x + threadIdx.x;
    if (idx < NN * RR) g_deg[idx] = 0;
    if (idx < BINS) g_hist[idx] = 0;
    if (idx < HF) { g_sum[idx] = 0.f; g_sumsq[idx] = 0.f; }
}
__global__ void zero_sums_kernel() {
    int idx = threadIdx.x;
    if (idx < HF) { g_sum[idx] = 0.f; g_sumsq[idx] = 0.f; }
}
__global__ void deg_hist_kernel(const int* __restrict__ ei, const int* __restrict__ et) {
    int e = blockIdx.x * blockDim.x + threadIdx.x;
    if (e >= EE) return;
    int src = ei[e];
    int tgt = ei[EE + e];
    int t   = et[e];
    atomicAdd(&g_deg[tgt * RR + t], 1);
    atomicAdd(&g_hist[t * NN + src], 1);
}
// per-1024-bin block sums (+ fused inv-degree LUT)
__global__ void scan1_kernel() {
    __shared__ int sh[256];
    int base = blockIdx.x * 1024;
    int t = threadIdx.x;
    int s = 0;
#pragma unroll
    for (int j = 0; j < 4; j++) {
        int idx = base + t * 4 + j;
        if (idx < BINS) {
            s += g_hist[idx];
            int dg = g_deg[idx];
            g_invdeg[idx] = (dg > 0) ? 1.0f / (float)dg : 0.f;
        }
    }
    sh[t] = s;
    __syncthreads();
    for (int off = 128; off > 0; off >>= 1) {
        if (t < off) sh[t] += sh[t + off];
        __syncthreads();
    }
    if (t == 0) g_bsum[blockIdx.x] = sh[0];
}
// per-block exclusive scan + (self-computed) block offset -> g_hcur
__global__ void scan3_kernel() {
    __shared__ int sh[256];
    __shared__ int offs;
    int t = threadIdx.x;
    // block offset = sum of bsum[0..blockIdx-1]
    int part = 0;
    for (int i = t; i < blockIdx.x; i += 256) part += g_bsum[i];
    sh[t] = part;
    __syncthreads();
    for (int off = 128; off > 0; off >>= 1) {
        if (t < off) sh[t] += sh[t + off];
        __syncthreads();
    }
    if (t == 0) offs = sh[0];
    __syncthreads();

    int base = blockIdx.x * 1024;
    int loc[4];
    int s = 0;
#pragma unroll
    for (int j = 0; j < 4; j++) {
        int idx = base + t * 4 + j;
        loc[j] = s;
        s += (idx < BINS) ? g_hist[idx] : 0;
    }
    sh[t] = s;
    __syncthreads();
    for (int off = 1; off < 256; off <<= 1) {
        int v = (t >= off) ? sh[t - off] : 0;
        __syncthreads();
        sh[t] += v;
        __syncthreads();
    }
    int texc = sh[t] - s + offs;
#pragma unroll
    for (int j = 0; j < 4; j++) {
        int idx = base + t * 4 + j;
        if (idx < BINS) g_hcur[idx] = texc + loc[j];
    }
}
__global__ void place_kernel(const int* __restrict__ ei, const int* __restrict__ et) {
    int e = blockIdx.x * blockDim.x + threadIdx.x;
    if (e >= EE) return;
    int src = ei[e];
    int tgt = ei[EE + e];
    int t   = et[e];
    int pos = atomicAdd(&g_hcur[t * NN + src], 1);
    g_etgt[pos] = tgt;
}

// ---------------- BN stats / apply ------------------------------------------
__global__ void bn_stats_kernel() {
    int c = threadIdx.x & 127;
    int rstart = blockIdx.x * (blockDim.x >> 7) + (threadIdx.x >> 7);
    int rstep  = gridDim.x * (blockDim.x >> 7);
    float s = 0.f, ss = 0.f;
    for (int r = rstart; r < NN; r += rstep) {
        float v = g_agg[(size_t)r * HF + c];
        s += v;
        ss += v * v;
    }
    atomicAdd(&g_sum[c], s);
    atomicAdd(&g_sumsq[c], ss);
}
__global__ void bn_apply_kernel(const float* __restrict__ gamma,
                                const float* __restrict__ beta) {
    int idx = blockIdx.x * blockDim.x + threadIdx.x;
    if (idx >= NN * HF) return;
    int c = idx & 127;
    const float invN = 1.0f / (float)NN;
    float mean = g_sum[c] * invN;
    float var  = fmaxf(g_sumsq[c] * invN - mean * mean, 0.f);
    float v = (g_agg[idx] - mean) * rsqrtf(var + BN_EPS) * gamma[c] + beta[c];
    v = fmaxf(v, 0.f);
    __nv_bfloat16 h = __float2bfloat16_rn(v);
    g_xhi[idx] = h;
    g_xlo[idx] = __float2bfloat16_rn(v - __bfloat162float(h));
}

// ---------------- classifier: out[N,2] = (hi+lo) @ cw + cb ------------------
__global__ void classifier_kernel(const float* __restrict__ cw,
                                  const float* __restrict__ cb,
                                  float* __restrict__ out) {
    __shared__ float wsm[HF * OUTF];
    if (threadIdx.x < HF * OUTF) wsm[threadIdx.x] = cw[threadIdx.x];
    __syncthreads();
    int w = (blockIdx.x * blockDim.x + threadIdx.x) >> 5;
    if (w >= NN) return;
    int lane = threadIdx.x & 31;
    const __nv_bfloat162* ph = reinterpret_cast<const __nv_bfloat162*>(
        g_xhi + (size_t)w * HF + lane * 4);
    const __nv_bfloat162* pl = reinterpret_cast<const __nv_bfloat162*>(
        g_xlo + (size_t)w * HF + lane * 4);
    __nv_bfloat162 h0 = ph[0], h1 = ph[1], l0 = pl[0], l1 = pl[1];
    float vx = __bfloat162float(h0.x) + __bfloat162float(l0.x);
    float vy = __bfloat162float(h0.y) + __bfloat162float(l0.y);
    float vz = __bfloat162float(h1.x) + __bfloat162float(l1.x);
    float vw = __bfloat162float(h1.y) + __bfloat162float(l1.y);
    int c = lane * 4;
    float o0 = vx * wsm[(c + 0) * 2]     + vy * wsm[(c + 1) * 2]
             + vz * wsm[(c + 2) * 2]     + vw * wsm[(c + 3) * 2];
    float o1 = vx * wsm[(c + 0) * 2 + 1] + vy * wsm[(c + 1) * 2 + 1]
             + vz * wsm[(c + 2) * 2 + 1] + vw * wsm[(c + 3) * 2 + 1];
#pragma unroll
    for (int off = 16; off > 0; off >>= 1) {
        o0 += __shfl_down_sync(0xFFFFFFFFu, o0, off);
        o1 += __shfl_down_sync(0xFFFFFFFFu, o1, off);
    }
    if (lane == 0) {
        out[(size_t)w * 2 + 0] = o0 + cb[0];
        out[(size_t)w * 2 + 1] = o1 + cb[1];
    }
}

// ================================ launch =====================================
extern "C" void kernel_launch(void* const* d_in, const int* in_sizes, int n_in,
                              void* d_out, int out_size) {
    const float* x    = (const float*)d_in[0];
    const int*   ei   = (const int*)d_in[1];
    const int*   et   = (const int*)d_in[2];
    const float* w1   = (const float*)d_in[3];
    const float* r1   = (const float*)d_in[4];
    const float* b1   = (const float*)d_in[5];
    const float* g1   = (const float*)d_in[6];
    const float* be1  = (const float*)d_in[7];
    const float* w2   = (const float*)d_in[8];
    const float* r2   = (const float*)d_in[9];
    const float* b2   = (const float*)d_in[10];
    const float* g2   = (const float*)d_in[11];
    const float* be2  = (const float*)d_in[12];
    const float* cw   = (const float*)d_in[13];
    const float* cb   = (const float*)d_in[14];
    float* out = (float*)d_out;

    cudaFuncSetAttribute(root_gemm_kernel,
                         cudaFuncAttributeMaxDynamicSharedMemorySize, SMEM_BYTES);
    cudaFuncSetAttribute(gemm_scatter_kernel,
                         cudaFuncAttributeMaxDynamicSharedMemorySize, SMEM_BYTES);

    int bn_apply_blocks = (NN * HF + 255) / 256;
    int cls_blocks      = (NN * 32 + 255) / 256;
    int splitx_blocks   = (NN * HF + 255) / 256;
    int splitw_blocks   = (9 * 16384 + 255) / 256;
    int edge_blocks     = (EE + 255) / 256;

    // 1-2: splits   3-5: prep (hist half)   6: root GEMM (ncu -s 5 captures this)
    split_w_kernel<<<splitw_blocks, 256>>>(w1, r1);
    split_x_kernel<<<splitx_blocks, 256>>>(x);
    zero_prep_kernel<<<(BINS + 255) / 256, 256>>>();
    deg_hist_kernel<<<edge_blocks, 256>>>(ei, et);
    scan1_kernel<<<SCAN_BLOCKS, 256>>>();
    root_gemm_kernel<<<GEMM_TILES, 256, SMEM_BYTES>>>(b1);   // agg = x@root + b
    // 7-8: prep (scan/place) — must finish before fused kernel
    scan3_kernel<<<SCAN_BLOCKS, 256>>>();
    place_kernel<<<edge_blocks, 256>>>(ei, et);
    // 9: fused GEMM + scatter (mats 0..7, reds into agg)
    gemm_scatter_kernel<<<GEMM_TILES, 256, SMEM_BYTES>>>();
    bn_stats_kernel<<<256, 256>>>();
    bn_apply_kernel<<<bn_apply_blocks, 256>>>(g1, be1);

    // ---- layer 2 (degree + sorted edges reused) ----
    zero_sums_kernel<<<1, 128>>>();
    split_w_kernel<<<splitw_blocks, 256>>>(w2, r2);
    root_gemm_kernel<<<GEMM_TILES, 256, SMEM_BYTES>>>(b2);
    gemm_scatter_kernel<<<GEMM_TILES, 256, SMEM_BYTES>>>();
    bn_stats_kernel<<<256, 256>>>();
    bn_apply_kernel<<<bn_apply_blocks, 256>>>(g2, be2);

    // ---- classifier ----
    classifier_kernel<<<cls_blocks, 256>>>(cw, cb, out);
}

// round 11
// speedup vs baseline: 1.4271x; 1.4271x over previous
#include <cuda_runtime.h>
#include <cuda_bf16.h>
#include <cstdint>

#define NN   50000
#define EE   800000
#define INF  128
#define HF   128
#define RR   8
#define OUTF 2
#define BN_EPS 1e-5f
#define GEMM_TILES ((NN + 63) / 64)     // 782 (BM=64)
#define BINS (RR * NN)                  // 400000 (type,src) bins
#define SCAN_BLOCKS ((BINS + 1023) / 1024)  // 391

// ---------------- scratch (device globals; no allocation allowed) ----------
__device__ float g_xw[(size_t)RR * NN * HF];        // [R][N][H] transformed
__device__ float g_agg[(size_t)NN * HF];            // pre-BN layer output
__device__ __nv_bfloat16 g_xhi[(size_t)NN * HF];    // bf16 hi split of acts
__device__ __nv_bfloat16 g_xlo[(size_t)NN * HF];    // bf16 lo split
__device__ __nv_bfloat16 g_whi[9 * 128 * 128];      // [mat][n][k] W^T, hi
__device__ __nv_bfloat16 g_wlo[9 * 128 * 128];      // lo
__device__ int   g_deg[NN * RR];
__device__ float g_invdeg[NN * RR];
__device__ float g_sum[HF];
__device__ float g_sumsq[HF];
// edge sorting by (type, src)
__device__ int   g_hist[BINS];      // per-bin counts
__device__ int   g_hcur[BINS];      // scan result -> cursors (end after place)
__device__ int   g_bsum[SCAN_BLOCKS];
__device__ int   g_etgt[EE];        // targets, sorted by (type, src)

// ======================= small helpers ======================================
__device__ __forceinline__ uint32_t smem_to_u32(const void* p) {
    uint32_t a;
    asm("{ .reg .u64 t; cvta.to.shared.u64 t, %1; cvt.u32.u64 %0, t; }"
        : "=r"(a) : "l"(p));
    return a;
}
__device__ __forceinline__ void cp16(uint32_t dst, const void* src) {
    asm volatile("cp.async.cg.shared.global [%0], [%1], 16;"
                 :: "r"(dst), "l"(__cvta_generic_to_global(src)));
}
__device__ __forceinline__ void mma_bf16(float d[4], const uint32_t a[4],
                                         uint32_t b0, uint32_t b1) {
    asm volatile(
        "mma.sync.aligned.m16n8k16.row.col.f32.bf16.bf16.f32 "
        "{%0,%1,%2,%3}, {%4,%5,%6,%7}, {%8,%9}, {%0,%1,%2,%3};"
        : "+f"(d[0]), "+f"(d[1]), "+f"(d[2]), "+f"(d[3])
        : "r"(a[0]), "r"(a[1]), "r"(a[2]), "r"(a[3]), "r"(b0), "r"(b1));
}
__device__ __forceinline__ void ldsm_x4(uint32_t r[4], uint32_t addr) {
    asm volatile("ldmatrix.sync.aligned.m8n8.x4.shared.b16 {%0,%1,%2,%3}, [%4];"
        : "=r"(r[0]), "=r"(r[1]), "=r"(r[2]), "=r"(r[3]) : "r"(addr));
}

// =============== SMEM layout (u32 units), stride 68 u32 = 136 bf16 ==========
#define SWU    68
#define ROWB   (SWU * 4)                   // 272 bytes per row
#define AH_U   0
#define AL_U   (64 * SWU)                  // 4352  (A tiles are 64 rows now)
#define B0_U   (2 * 64 * SWU)              // 8704
#define B1_U   (B0_U + 128 * SWU)          // 17408
#define SMEM_U32S   (B1_U + 128 * SWU)     // 26112
#define SMEM_BYTES  (SMEM_U32S * 4)        // 104448 -> 2 CTAs/SM

// prefetch one 128x128 bf16 tile (row-major [n][k]) into padded smem
__device__ __forceinline__ void prefetch_B(uint32_t sb, int bofs_u,
                                           const __nv_bfloat16* W) {
    int tid = threadIdx.x;
#pragma unroll
    for (int i = 0; i < 8; i++) {
        int e = i * 256 + tid;            // 0..2047 uint4s
        int row = e >> 4;                 // 0..127
        int q   = e & 15;                 // uint4 (8 bf16) within row
        cp16(sb + (uint32_t)(bofs_u + row * SWU + q * 4) * 4, W + row * 128 + q * 8);
    }
}

// one bf16 pass via ldmatrix: D += A x B^T over K=128 (warp tile 16x64)
__device__ __forceinline__ void do_pass(uint32_t aBase, uint32_t bBase,
                                        uint32_t aLane, uint32_t bLane,
                                        float d[8][4]) {
#pragma unroll
    for (int ks = 0; ks < 8; ks++) {
        uint32_t kb = (uint32_t)ks * 32;          // 16 bf16 = 32 bytes
        uint32_t a[4];
        ldsm_x4(a, aBase + aLane + kb);
#pragma unroll
        for (int p = 0; p < 4; p++) {
            uint32_t b[4];
            ldsm_x4(b, bBase + bLane + (uint32_t)(p * 16) * ROWB + kb);
            mma_bf16(d[2 * p],     a, b[0], b[1]);
            mma_bf16(d[2 * p + 1], a, b[2], b[3]);
        }
    }
}

// load A hi/lo tiles (64 rows) into smem, zero-padded past NN
__device__ __forceinline__ void load_A(uint32_t sb, uint32_t* smu, int m0) {
    int tid = threadIdx.x;
#pragma unroll
    for (int i = 0; i < 4; i++) {
        int e = i * 256 + tid;            // 0..1023 uint4s
        int row = e >> 4, q = e & 15;     // row 0..63
        uint32_t dh = sb + (uint32_t)(AH_U + row * SWU + q * 4) * 4;
        uint32_t dl = sb + (uint32_t)(AL_U + row * SWU + q * 4) * 4;
        if (m0 + row < NN) {
            cp16(dh, g_xhi + (size_t)(m0 + row) * 128 + q * 8);
            cp16(dl, g_xlo + (size_t)(m0 + row) * 128 + q * 8);
        } else {
            uint4 z = make_uint4(0, 0, 0, 0);
            *reinterpret_cast<uint4*>(smu + AH_U + row * SWU + q * 4) = z;
            *reinterpret_cast<uint4*>(smu + AL_U + row * SWU + q * 4) = z;
        }
    }
}

// ================== bf16 tensor GEMM: 9 matrices per 64-row M-tile ==========
// 8 warps: 4 in m (16 rows each) x 2 in n (64 cols each). 2 CTAs/SM.
__global__ void __launch_bounds__(256, 2) gemm_tc_kernel(const float* __restrict__ bias) {
    extern __shared__ uint32_t smu[];
    uint32_t sb = smem_to_u32(smu);
    const int tid = threadIdx.x;
    const int wid = tid >> 5, lane = tid & 31;
    const int wm = wid & 3, wn = wid >> 2;       // 4 x 2 warp grid (16x64 tiles)
    const int lr = lane >> 2, lc = lane & 3;
    const int m0 = blockIdx.x * 64;

    // A: row = wm*16 + (lane&15), k-half = lane>>4
    const uint32_t aLane = (uint32_t)(wm * 16 + (lane & 15)) * ROWB
                         + (uint32_t)(lane >> 4) * 16;
    // B: n row = wn*64 + ((lane>>4)&1)*8 + (lane&7) (+p*16), k-half = (lane>>3)&1
    const uint32_t bLane = (uint32_t)(wn * 64 + ((lane >> 4) & 1) * 8 + (lane & 7)) * ROWB
                         + (uint32_t)((lane >> 3) & 1) * 16;

    load_A(sb, smu, m0);
    prefetch_B(sb, B0_U, g_whi);    // B_hi(mat 0)
    asm volatile("cp.async.commit_group;" ::: "memory");
    asm volatile("cp.async.wait_group 0;" ::: "memory");
    __syncthreads();

    float d[8][4];
#pragma unroll
    for (int nt = 0; nt < 8; nt++)
#pragma unroll
        for (int j = 0; j < 4; j++) d[nt][j] = 0.f;

    const uint32_t ahB = sb + AH_U * 4;
    const uint32_t alB = sb + AL_U * 4;
    int stage = 0;
    // 18 tiles: even t = B_hi(t/2) [Ahi & Alo passes], odd t = B_lo(t/2) [Ahi pass]
    for (int t = 0; t < 18; t++) {
        if (t + 1 < 18) {
            int nm = (t + 1) >> 1;
            const __nv_bfloat16* Wn =
                ((t + 1) & 1) ? (g_wlo + nm * 16384) : (g_whi + nm * 16384);
            prefetch_B(sb, stage ? B0_U : B1_U, Wn);
        }
        asm volatile("cp.async.commit_group;" ::: "memory");

        const uint32_t bB = sb + (stage ? B1_U : B0_U) * 4;
        do_pass(ahB, bB, aLane, bLane, d);               // a_hi x b
        if (!(t & 1)) do_pass(alB, bB, aLane, bLane, d); // a_lo x b_hi

        if (t & 1) {
            int mat = t >> 1;
            float* gbase = (mat < 8) ? (g_xw + (size_t)mat * NN * HF) : g_agg;
            int r0 = m0 + wm * 16 + lr;
#pragma unroll
            for (int nt = 0; nt < 8; nt++) {
                int col = wn * 64 + (nt >> 1) * 16 + (nt & 1) * 8 + lc * 2;
                float b0 = 0.f, b1 = 0.f;
                if (mat == 8) { b0 = bias[col]; b1 = bias[col + 1]; }
                if (r0 < NN)
                    *reinterpret_cast<float2*>(gbase + (size_t)r0 * HF + col) =
                        make_float2(d[nt][0] + b0, d[nt][1] + b1);
                if (r0 + 8 < NN)
                    *reinterpret_cast<float2*>(gbase + (size_t)(r0 + 8) * HF + col) =
                        make_float2(d[nt][2] + b0, d[nt][3] + b1);
#pragma unroll
                for (int j = 0; j < 4; j++) d[nt][j] = 0.f;
            }
        }
        asm volatile("cp.async.wait_group 0;" ::: "memory");
        __syncthreads();
        stage ^= 1;
    }
}

// ======================= prep kernels ========================================
__global__ void split_x_kernel(const float* __restrict__ x_in) {
    size_t idx = (size_t)blockIdx.x * blockDim.x + threadIdx.x;
    if (idx >= (size_t)NN * HF) return;
    float v = x_in[idx];
    __nv_bfloat16 h = __float2bfloat16_rn(v);
    g_xhi[idx] = h;
    g_xlo[idx] = __float2bfloat16_rn(v - __bfloat162float(h));
}

// transpose W[mat][k][n] -> [mat][n][k], split hi/lo bf16. mat 8 = root.
__global__ void split_w_kernel(const float* __restrict__ w, const float* __restrict__ root) {
    int idx = blockIdx.x * blockDim.x + threadIdx.x;
    if (idx >= 9 * 16384) return;
    int mat = idx >> 14;
    int n = (idx >> 7) & 127;
    int k = idx & 127;
    float v = (mat < 8) ? w[(mat << 14) + (k << 7) + n] : root[(k << 7) + n];
    __nv_bfloat16 h = __float2bfloat16_rn(v);
    g_whi[idx] = h;
    g_wlo[idx] = __float2bfloat16_rn(v - __bfloat162float(h));
}

__global__ void zero_prep_kernel() {
    int idx = blockIdx.x * blockDim.x + threadIdx.x;
    if (idx < NN * RR) g_deg[idx] = 0;
    if (idx < BINS) g_hist[idx] = 0;
    if (idx < HF) { g_sum[idx] = 0.f; g_sumsq[idx] = 0.f; }
}
__global__ void zero_sums_kernel() {
    int idx = threadIdx.x;
    if (idx < HF) { g_sum[idx] = 0.f; g_sumsq[idx] = 0.f; }
}
__global__ void deg_hist_kernel(const int* __restrict__ ei, const int* __restrict__ et) {
    int e = blockIdx.x * blockDim.x + threadIdx.x;
    if (e >= EE) return;
    int src = ei[e];
    int tgt = ei[EE + e];
    int t   = et[e];
    atomicAdd(&g_deg[tgt * RR + t], 1);
    atomicAdd(&g_hist[t * NN + src], 1);
}
// per-1024-bin block sums (+ fused inv-degree LUT)
__global__ void scan1_kernel() {
    __shared__ int sh[256];
    int base = blockIdx.x * 1024;
    int t = threadIdx.x;
    int s = 0;
#pragma unroll
    for (int j = 0; j < 4; j++) {
        int idx = base + t * 4 + j;
        if (idx < BINS) {
            s += g_hist[idx];
            int dg = g_deg[idx];
            g_invdeg[idx] = (dg > 0) ? 1.0f / (float)dg : 0.f;
        }
    }
    sh[t] = s;
    __syncthreads();
    for (int off = 128; off > 0; off >>= 1) {
        if (t < off) sh[t] += sh[t + off];
        __syncthreads();
    }
    if (t == 0) g_bsum[blockIdx.x] = sh[0];
}
// per-block exclusive scan + self-computed block offset -> g_hcur
__global__ void scan3_kernel() {
    __shared__ int sh[256];
    __shared__ int offs;
    int t = threadIdx.x;
    int part = 0;
    for (int i = t; i < blockIdx.x; i += 256) part += g_bsum[i];
    sh[t] = part;
    __syncthreads();
    for (int off = 128; off > 0; off >>= 1) {
        if (t < off) sh[t] += sh[t + off];
        __syncthreads();
    }
    if (t == 0) offs = sh[0];
    __syncthreads();

    int base = blockIdx.x * 1024;
    int loc[4];
    int s = 0;
#pragma unroll
    for (int j = 0; j < 4; j++) {
        int idx = base + t * 4 + j;
        loc[j] = s;
        s += (idx < BINS) ? g_hist[idx] : 0;
    }
    sh[t] = s;
    __syncthreads();
    for (int off = 1; off < 256; off <<= 1) {
        int v = (t >= off) ? sh[t - off] : 0;
        __syncthreads();
        sh[t] += v;
        __syncthreads();
    }
    int texc = sh[t] - s + offs;
#pragma unroll
    for (int j = 0; j < 4; j++) {
        int idx = base + t * 4 + j;
        if (idx < BINS) g_hcur[idx] = texc + loc[j];
    }
}
__global__ void place_kernel(const int* __restrict__ ei, const int* __restrict__ et) {
    int e = blockIdx.x * blockDim.x + threadIdx.x;
    if (e >= EE) return;
    int src = ei[e];
    int tgt = ei[EE + e];
    int t   = et[e];
    int pos = atomicAdd(&g_hcur[t * NN + src], 1);
    g_etgt[pos] = tgt;
}

// -------- bin scatter: one warp per (type,src) bin; gather once, red per tgt -
__global__ void scatter_kernel() {
    int b = (blockIdx.x * blockDim.x + threadIdx.x) >> 5;   // bin id
    if (b >= BINS) return;
    int cnt = g_hist[b];
    if (cnt == 0) return;
    int lane = threadIdx.x & 31;
    int end   = g_hcur[b];          // cursor advanced to bin end by place
    int start = end - cnt;
    int t   = b / NN;
    int src = b - t * NN;
    float4 v = *reinterpret_cast<const float4*>(
        g_xw + ((size_t)t * NN + src) * HF + lane * 4);
    for (int i = start; i < end; i++) {
        int tgt = __ldg(&g_etgt[i]);
        float inv = __ldg(&g_invdeg[tgt * RR + t]);
        float* dst = g_agg + (size_t)tgt * HF + lane * 4;
        asm volatile("red.global.add.v4.f32 [%0], {%1, %2, %3, %4};"
            :: "l"(__cvta_generic_to_global(dst)),
               "f"(v.x * inv), "f"(v.y * inv), "f"(v.z * inv), "f"(v.w * inv)
            : "memory");
    }
}

// ---------------- BN stats / apply ------------------------------------------
__global__ void bn_stats_kernel() {
    int c = threadIdx.x & 127;
    int rstart = blockIdx.x * (blockDim.x >> 7) + (threadIdx.x >> 7);
    int rstep  = gridDim.x * (blockDim.x >> 7);
    float s = 0.f, ss = 0.f;
    for (int r = rstart; r < NN; r += rstep) {
        float v = g_agg[(size_t)r * HF + c];
        s += v;
        ss += v * v;
    }
    atomicAdd(&g_sum[c], s);
    atomicAdd(&g_sumsq[c], ss);
}
__global__ void bn_apply_kernel(const float* __restrict__ gamma,
                                const float* __restrict__ beta) {
    int idx = blockIdx.x * blockDim.x + threadIdx.x;
    if (idx >= NN * HF) return;
    int c = idx & 127;
    const float invN = 1.0f / (float)NN;
    float mean = g_sum[c] * invN;
    float var  = fmaxf(g_sumsq[c] * invN - mean * mean, 0.f);
    float v = (g_agg[idx] - mean) * rsqrtf(var + BN_EPS) * gamma[c] + beta[c];
    v = fmaxf(v, 0.f);
    __nv_bfloat16 h = __float2bfloat16_rn(v);
    g_xhi[idx] = h;
    g_xlo[idx] = __float2bfloat16_rn(v - __bfloat162float(h));
}

// ---------------- classifier: out[N,2] = (hi+lo) @ cw + cb ------------------
__global__ void classifier_kernel(const float* __restrict__ cw,
                                  const float* __restrict__ cb,
                                  float* __restrict__ out) {
    __shared__ float wsm[HF * OUTF];
    if (threadIdx.x < HF * OUTF) wsm[threadIdx.x] = cw[threadIdx.x];
    __syncthreads();
    int w = (blockIdx.x * blockDim.x + threadIdx.x) >> 5;
    if (w >= NN) return;
    int lane = threadIdx.x & 31;
    const __nv_bfloat162* ph = reinterpret_cast<const __nv_bfloat162*>(
        g_xhi + (size_t)w * HF + lane * 4);
    const __nv_bfloat162* pl = reinterpret_cast<const __nv_bfloat162*>(
        g_xlo + (size_t)w * HF + lane * 4);
    __nv_bfloat162 h0 = ph[0], h1 = ph[1], l0 = pl[0], l1 = pl[1];
    float vx = __bfloat162float(h0.x) + __bfloat162float(l0.x);
    float vy = __bfloat162float(h0.y) + __bfloat162float(l0.y);
    float vz = __bfloat162float(h1.x) + __bfloat162float(l1.x);
    float vw = __bfloat162float(h1.y) + __bfloat162float(l1.y);
    int c = lane * 4;
    float o0 = vx * wsm[(c + 0) * 2]     + vy * wsm[(c + 1) * 2]
             + vz * wsm[(c + 2) * 2]     + vw * wsm[(c + 3) * 2];
    float o1 = vx * wsm[(c + 0) * 2 + 1] + vy * wsm[(c + 1) * 2 + 1]
             + vz * wsm[(c + 2) * 2 + 1] + vw * wsm[(c + 3) * 2 + 1];
#pragma unroll
    for (int off = 16; off > 0; off >>= 1) {
        o0 += __shfl_down_sync(0xFFFFFFFFu, o0, off);
        o1 += __shfl_down_sync(0xFFFFFFFFu, o1, off);
    }
    if (lane == 0) {
        out[(size_t)w * 2 + 0] = o0 + cb[0];
        out[(size_t)w * 2 + 1] = o1 + cb[1];
    }
}

// ================================ launch =====================================
extern "C" void kernel_launch(void* const* d_in, const int* in_sizes, int n_in,
                              void* d_out, int out_size) {
    const float* x    = (const float*)d_in[0];
    const int*   ei   = (const int*)d_in[1];
    const int*   et   = (const int*)d_in[2];
    const float* w1   = (const float*)d_in[3];
    const float* r1   = (const float*)d_in[4];
    const float* b1   = (const float*)d_in[5];
    const float* g1   = (const float*)d_in[6];
    const float* be1  = (const float*)d_in[7];
    const float* w2   = (const float*)d_in[8];
    const float* r2   = (const float*)d_in[9];
    const float* b2   = (const float*)d_in[10];
    const float* g2   = (const float*)d_in[11];
    const float* be2  = (const float*)d_in[12];
    const float* cw   = (const float*)d_in[13];
    const float* cb   = (const float*)d_in[14];
    float* out = (float*)d_out;

    cudaFuncSetAttribute(gemm_tc_kernel,
                         cudaFuncAttributeMaxDynamicSharedMemorySize, SMEM_BYTES);

    int scatter_blocks  = (BINS * 32 + 255) / 256;   // warp per bin
    int bn_apply_blocks = (NN * HF + 255) / 256;
    int cls_blocks      = (NN * 32 + 255) / 256;
    int splitx_blocks   = (NN * HF + 255) / 256;
    int splitw_blocks   = (9 * 16384 + 255) / 256;
    int edge_blocks     = (EE + 255) / 256;

    // ncu empirically captures the 4th kernel launch -> GEMM goes in slot 4.
    split_w_kernel<<<splitw_blocks, 256>>>(w1, r1);            // 1
    split_x_kernel<<<splitx_blocks, 256>>>(x);                 // 2
    zero_prep_kernel<<<(BINS + 255) / 256, 256>>>();           // 3
    gemm_tc_kernel<<<GEMM_TILES, 256, SMEM_BYTES>>>(b1);       // 4 <- profiled
    deg_hist_kernel<<<edge_blocks, 256>>>(ei, et);             // 5
    scan1_kernel<<<SCAN_BLOCKS, 256>>>();                      // 6
    scan3_kernel<<<SCAN_BLOCKS, 256>>>();                      // 7
    place_kernel<<<edge_blocks, 256>>>(ei, et);                // 8
    scatter_kernel<<<scatter_blocks, 256>>>();                 // 9
    bn_stats_kernel<<<256, 256>>>();                           // 10
    bn_apply_kernel<<<bn_apply_blocks, 256>>>(g1, be1);        // 11

    // ---- layer 2 (degree + sorted edges reused) ----
    zero_sums_kernel<<<1, 128>>>();
    split_w_kernel<<<splitw_blocks, 256>>>(w2, r2);
    gemm_tc_kernel<<<GEMM_TILES, 256, SMEM_BYTES>>>(b2);
    scatter_kernel<<<scatter_blocks, 256>>>();
    bn_stats_kernel<<<256, 256>>>();
    bn_apply_kernel<<<bn_apply_blocks, 256>>>(g2, be2);

    // ---- classifier ----
    classifier_kernel<<<cls_blocks, 256>>>(cw, cb, out);
}

// round 12
// speedup vs baseline: 1.5118x; 1.0593x over previous
#include <cuda_runtime.h>
#include <cuda_bf16.h>
#include <cstdint>

#define NN   50000
#define EE   800000
#define INF  128
#define HF   128
#define RR   8
#define OUTF 2
#define BN_EPS 1e-5f
#define GEMM_TILES ((NN + 127) / 128)   // 391 (BM=128)
#define BINS (RR * NN)                  // 400000 (type,src) bins
#define SCAN_BLOCKS ((BINS + 1023) / 1024)  // 391

// ---------------- scratch (device globals; no allocation allowed) ----------
__device__ float g_xw[(size_t)RR * NN * HF];        // [R][N][H] transformed
__device__ float g_agg[(size_t)NN * HF];            // pre-BN layer output
__device__ __nv_bfloat16 g_xhi[(size_t)NN * HF];    // bf16 hi split of acts
__device__ __nv_bfloat16 g_xlo[(size_t)NN * HF];    // bf16 lo split
__device__ __nv_bfloat16 g_whi[9 * 128 * 128];      // [mat][n][k] W^T, hi
__device__ __nv_bfloat16 g_wlo[9 * 128 * 128];      // lo
__device__ int   g_deg[NN * RR];
__device__ float g_invdeg[NN * RR];
__device__ float g_sum[HF];
__device__ float g_sumsq[HF];
// edge sorting by (type, src)
__device__ int   g_hist[BINS];      // per-bin counts
__device__ int   g_hcur[BINS];      // scan result -> cursors (end after place)
__device__ int   g_bsum[SCAN_BLOCKS];
__device__ int   g_etgt[EE];        // targets, sorted by (type, src)

// ======================= small helpers ======================================
__device__ __forceinline__ uint32_t smem_to_u32(const void* p) {
    uint32_t a;
    asm("{ .reg .u64 t; cvta.to.shared.u64 t, %1; cvt.u32.u64 %0, t; }"
        : "=r"(a) : "l"(p));
    return a;
}
__device__ __forceinline__ void cp16(uint32_t dst, const void* src) {
    asm volatile("cp.async.cg.shared.global [%0], [%1], 16;"
                 :: "r"(dst), "l"(__cvta_generic_to_global(src)));
}
__device__ __forceinline__ void mma_bf16(float d[4], const uint32_t a[4],
                                         uint32_t b0, uint32_t b1) {
    asm volatile(
        "mma.sync.aligned.m16n8k16.row.col.f32.bf16.bf16.f32 "
        "{%0,%1,%2,%3}, {%4,%5,%6,%7}, {%8,%9}, {%0,%1,%2,%3};"
        : "+f"(d[0]), "+f"(d[1]), "+f"(d[2]), "+f"(d[3])
        : "r"(a[0]), "r"(a[1]), "r"(a[2]), "r"(a[3]), "r"(b0), "r"(b1));
}
__device__ __forceinline__ void ldsm_x4(uint32_t r[4], uint32_t addr) {
    asm volatile("ldmatrix.sync.aligned.m8n8.x4.shared.b16 {%0,%1,%2,%3}, [%4];"
        : "=r"(r[0]), "=r"(r[1]), "=r"(r[2]), "=r"(r[3]) : "r"(addr));
}

// =============== SMEM layout (u32 units), stride 68 u32 = 136 bf16 ==========
#define SWU    68
#define ROWB   (SWU * 4)                   // 272 bytes per row
#define AH_U   0
#define AL_U   (128 * SWU)                 // 8704
#define B_U    (2 * 128 * SWU)             // 17408 (single B buffer)
#define SMEM_U32S   (B_U + 128 * SWU)      // 26112
#define SMEM_BYTES  (SMEM_U32S * 4)        // 104448 -> 2 CTAs/SM

// prefetch one 128x128 bf16 tile (row-major [n][k]) into padded smem
__device__ __forceinline__ void prefetch_B(uint32_t sb, int bofs_u,
                                           const __nv_bfloat16* W) {
    int tid = threadIdx.x;
#pragma unroll
    for (int i = 0; i < 8; i++) {
        int e = i * 256 + tid;            // 0..2047 uint4s
        int row = e >> 4;                 // 0..127
        int q   = e & 15;                 // uint4 (8 bf16) within row
        cp16(sb + (uint32_t)(bofs_u + row * SWU + q * 4) * 4, W + row * 128 + q * 8);
    }
}

// one bf16 pass via ldmatrix: D += A x B^T over K=128 (warp tile 64x32)
__device__ __forceinline__ void do_pass(uint32_t aBase, uint32_t bBase,
                                        uint32_t aLane, uint32_t bLane,
                                        float d[4][4][4]) {
#pragma unroll
    for (int ks = 0; ks < 8; ks++) {
        uint32_t kb = (uint32_t)ks * 32;          // 16 bf16 = 32 bytes
        uint32_t a[4][4];
#pragma unroll
        for (int mt = 0; mt < 4; mt++)
            ldsm_x4(a[mt], aBase + aLane + (uint32_t)(mt * 16) * ROWB + kb);
#pragma unroll
        for (int p = 0; p < 2; p++) {
            uint32_t b[4];
            ldsm_x4(b, bBase + bLane + (uint32_t)(p * 16) * ROWB + kb);
#pragma unroll
            for (int mt = 0; mt < 4; mt++) {
                mma_bf16(d[mt][2 * p],     a[mt], b[0], b[1]);
                mma_bf16(d[mt][2 * p + 1], a[mt], b[2], b[3]);
            }
        }
    }
}

// load A hi/lo tiles (128 rows) into smem, zero-padded past NN
__device__ __forceinline__ void load_A(uint32_t sb, uint32_t* smu, int m0) {
    int tid = threadIdx.x;
#pragma unroll
    for (int i = 0; i < 8; i++) {
        int e = i * 256 + tid;
        int row = e >> 4, q = e & 15;
        uint32_t dh = sb + (uint32_t)(AH_U + row * SWU + q * 4) * 4;
        uint32_t dl = sb + (uint32_t)(AL_U + row * SWU + q * 4) * 4;
        if (m0 + row < NN) {
            cp16(dh, g_xhi + (size_t)(m0 + row) * 128 + q * 8);
            cp16(dl, g_xlo + (size_t)(m0 + row) * 128 + q * 8);
        } else {
            uint4 z = make_uint4(0, 0, 0, 0);
            *reinterpret_cast<uint4*>(smu + AH_U + row * SWU + q * 4) = z;
            *reinterpret_cast<uint4*>(smu + AL_U + row * SWU + q * 4) = z;
        }
    }
}

// ================== bf16 tensor GEMM: 9 matrices per 128-row M-tile =========
// 8 warps (2m x 4n, 64x32 warp tiles), single B buffer, 2 CTAs/SM.
// B-load stalls of one CTA overlap MMA phases of the co-resident CTA.
__global__ void __launch_bounds__(256, 2) gemm_tc_kernel(const float* __restrict__ bias) {
    extern __shared__ uint32_t smu[];
    uint32_t sb = smem_to_u32(smu);
    const int tid = threadIdx.x;
    const int wid = tid >> 5, lane = tid & 31;
    const int wm = wid & 1, wn = wid >> 1;       // 2 x 4 warp grid (64x32 tiles)
    const int lr = lane >> 2, lc = lane & 3;
    const int m0 = blockIdx.x * 128;

    // A: row = wm*64 + (lane&15) (+mt*16), k-half = lane>>4
    const uint32_t aLane = (uint32_t)(wm * 64 + (lane & 15)) * ROWB
                         + (uint32_t)(lane >> 4) * 16;
    // B: n row = wn*32 + ((lane>>4)&1)*8 + (lane&7) (+p*16), k-half = (lane>>3)&1
    const uint32_t bLane = (uint32_t)(wn * 32 + ((lane >> 4) & 1) * 8 + (lane & 7)) * ROWB
                         + (uint32_t)((lane >> 3) & 1) * 16;

    load_A(sb, smu, m0);
    asm volatile("cp.async.commit_group;" ::: "memory");
    asm volatile("cp.async.wait_group 0;" ::: "memory");
    __syncthreads();

    float d[4][4][4];
#pragma unroll
    for (int mt = 0; mt < 4; mt++)
#pragma unroll
        for (int nt = 0; nt < 4; nt++)
#pragma unroll
            for (int j = 0; j < 4; j++) d[mt][nt][j] = 0.f;

    const uint32_t ahB = sb + AH_U * 4;
    const uint32_t alB = sb + AL_U * 4;
    const uint32_t bB  = sb + B_U * 4;

    for (int mat = 0; mat < 9; mat++) {
        // ---- B_hi ----
        prefetch_B(sb, B_U, g_whi + mat * 16384);
        asm volatile("cp.async.commit_group;" ::: "memory");
        asm volatile("cp.async.wait_group 0;" ::: "memory");
        __syncthreads();
        do_pass(ahB, bB, aLane, bLane, d);     // hi*hi
        do_pass(alB, bB, aLane, bLane, d);     // lo*hi
        __syncthreads();                        // B reads done
        // ---- B_lo ----
        prefetch_B(sb, B_U, g_wlo + mat * 16384);
        asm volatile("cp.async.commit_group;" ::: "memory");
        asm volatile("cp.async.wait_group 0;" ::: "memory");
        __syncthreads();
        do_pass(ahB, bB, aLane, bLane, d);     // hi*lo

        // ---- writeout (registers only; B safe to overwrite after sync) ----
        float* gbase = (mat < 8) ? (g_xw + (size_t)mat * NN * HF) : g_agg;
#pragma unroll
        for (int mt = 0; mt < 4; mt++) {
            int r0 = m0 + wm * 64 + mt * 16 + lr;
#pragma unroll
            for (int nt = 0; nt < 4; nt++) {
                int col = wn * 32 + nt * 8 + lc * 2;
                float b0 = 0.f, b1 = 0.f;
                if (mat == 8) { b0 = bias[col]; b1 = bias[col + 1]; }
                if (r0 < NN)
                    *reinterpret_cast<float2*>(gbase + (size_t)r0 * HF + col) =
                        make_float2(d[mt][nt][0] + b0, d[mt][nt][1] + b1);
                if (r0 + 8 < NN)
                    *reinterpret_cast<float2*>(gbase + (size_t)(r0 + 8) * HF + col) =
                        make_float2(d[mt][nt][2] + b0, d[mt][nt][3] + b1);
#pragma unroll
                for (int j = 0; j < 4; j++) d[mt][nt][j] = 0.f;
            }
        }
        __syncthreads();                        // B reads done before next prefetch
    }
}

// ======================= prep kernels ========================================
__global__ void split_x_kernel(const float* __restrict__ x_in) {
    size_t idx = (size_t)blockIdx.x * blockDim.x + threadIdx.x;
    if (idx >= (size_t)NN * HF) return;
    float v = x_in[idx];
    __nv_bfloat16 h = __float2bfloat16_rn(v);
    g_xhi[idx] = h;
    g_xlo[idx] = __float2bfloat16_rn(v - __bfloat162float(h));
}

// transpose W[mat][k][n] -> [mat][n][k], split hi/lo bf16. mat 8 = root.
__global__ void split_w_kernel(const float* __restrict__ w, const float* __restrict__ root) {
    int idx = blockIdx.x * blockDim.x + threadIdx.x;
    if (idx >= 9 * 16384) return;
    int mat = idx >> 14;
    int n = (idx >> 7) & 127;
    int k = idx & 127;
    float v = (mat < 8) ? w[(mat << 14) + (k << 7) + n] : root[(k << 7) + n];
    __nv_bfloat16 h = __float2bfloat16_rn(v);
    g_whi[idx] = h;
    g_wlo[idx] = __float2bfloat16_rn(v - __bfloat162float(h));
}

__global__ void zero_prep_kernel() {
    int idx = blockIdx.x * blockDim.x + threadIdx.x;
    if (idx < NN * RR) g_deg[idx] = 0;
    if (idx < BINS) g_hist[idx] = 0;
    if (idx < HF) { g_sum[idx] = 0.f; g_sumsq[idx] = 0.f; }
}
__global__ void zero_sums_kernel() {
    int idx = threadIdx.x;
    if (idx < HF) { g_sum[idx] = 0.f; g_sumsq[idx] = 0.f; }
}
__global__ void deg_hist_kernel(const int* __restrict__ ei, const int* __restrict__ et) {
    int e = blockIdx.x * blockDim.x + threadIdx.x;
    if (e >= EE) return;
    int src = ei[e];
    int tgt = ei[EE + e];
    int t   = et[e];
    atomicAdd(&g_deg[tgt * RR + t], 1);
    atomicAdd(&g_hist[t * NN + src], 1);
}
// per-1024-bin block sums (+ fused inv-degree LUT)
__global__ void scan1_kernel() {
    __shared__ int sh[256];
    int base = blockIdx.x * 1024;
    int t = threadIdx.x;
    int s = 0;
#pragma unroll
    for (int j = 0; j < 4; j++) {
        int idx = base + t * 4 + j;
        if (idx < BINS) {
            s += g_hist[idx];
            int dg = g_deg[idx];
            g_invdeg[idx] = (dg > 0) ? 1.0f / (float)dg : 0.f;
        }
    }
    sh[t] = s;
    __syncthreads();
    for (int off = 128; off > 0; off >>= 1) {
        if (t < off) sh[t] += sh[t + off];
        __syncthreads();
    }
    if (t == 0) g_bsum[blockIdx.x] = sh[0];
}
// per-block exclusive scan + self-computed block offset -> g_hcur
__global__ void scan3_kernel() {
    __shared__ int sh[256];
    __shared__ int offs;
    int t = threadIdx.x;
    int part = 0;
    for (int i = t; i < blockIdx.x; i += 256) part += g_bsum[i];
    sh[t] = part;
    __syncthreads();
    for (int off = 128; off > 0; off >>= 1) {
        if (t < off) sh[t] += sh[t + off];
        __syncthreads();
    }
    if (t == 0) offs = sh[0];
    __syncthreads();

    int base = blockIdx.x * 1024;
    int loc[4];
    int s = 0;
#pragma unroll
    for (int j = 0; j < 4; j++) {
        int idx = base + t * 4 + j;
        loc[j] = s;
        s += (idx < BINS) ? g_hist[idx] : 0;
    }
    sh[t] = s;
    __syncthreads();
    for (int off = 1; off < 256; off <<= 1) {
        int v = (t >= off) ? sh[t - off] : 0;
        __syncthreads();
        sh[t] += v;
        __syncthreads();
    }
    int texc = sh[t] - s + offs;
#pragma unroll
    for (int j = 0; j < 4; j++) {
        int idx = base + t * 4 + j;
        if (idx < BINS) g_hcur[idx] = texc + loc[j];
    }
}
__global__ void place_kernel(const int* __restrict__ ei, const int* __restrict__ et) {
    int e = blockIdx.x * blockDim.x + threadIdx.x;
    if (e >= EE) return;
    int src = ei[e];
    int tgt = ei[EE + e];
    int t   = et[e];
    int pos = atomicAdd(&g_hcur[t * NN + src], 1);
    g_etgt[pos] = tgt;
}

// -------- bin scatter: one warp per (type,src) bin; gather once, red per tgt -
__global__ void scatter_kernel() {
    int b = (blockIdx.x * blockDim.x + threadIdx.x) >> 5;   // bin id
    if (b >= BINS) return;
    int cnt = g_hist[b];
    if (cnt == 0) return;
    int lane = threadIdx.x & 31;
    int end   = g_hcur[b];          // cursor advanced to bin end by place
    int start = end - cnt;
    int t   = b / NN;
    int src = b - t * NN;
    float4 v = *reinterpret_cast<const float4*>(
        g_xw + ((size_t)t * NN + src) * HF + lane * 4);
    for (int i = start; i < end; i++) {
        int tgt = __ldg(&g_etgt[i]);
        float inv = __ldg(&g_invdeg[tgt * RR + t]);
        float* dst = g_agg + (size_t)tgt * HF + lane * 4;
        asm volatile("red.global.add.v4.f32 [%0], {%1, %2, %3, %4};"
            :: "l"(__cvta_generic_to_global(dst)),
               "f"(v.x * inv), "f"(v.y * inv), "f"(v.z * inv), "f"(v.w * inv)
            : "memory");
    }
}

// ---------------- BN stats / apply ------------------------------------------
__global__ void bn_stats_kernel() {
    int c = threadIdx.x & 127;
    int rstart = blockIdx.x * (blockDim.x >> 7) + (threadIdx.x >> 7);
    int rstep  = gridDim.x * (blockDim.x >> 7);
    float s = 0.f, ss = 0.f;
    for (int r = rstart; r < NN; r += rstep) {
        float v = g_agg[(size_t)r * HF + c];
        s += v;
        ss += v * v;
    }
    atomicAdd(&g_sum[c], s);
    atomicAdd(&g_sumsq[c], ss);
}
__global__ void bn_apply_kernel(const float* __restrict__ gamma,
                                const float* __restrict__ beta) {
    int idx = blockIdx.x * blockDim.x + threadIdx.x;
    if (idx >= NN * HF) return;
    int c = idx & 127;
    const float invN = 1.0f / (float)NN;
    float mean = g_sum[c] * invN;
    float var  = fmaxf(g_sumsq[c] * invN - mean * mean, 0.f);
    float v = (g_agg[idx] - mean) * rsqrtf(var + BN_EPS) * gamma[c] + beta[c];
    v = fmaxf(v, 0.f);
    __nv_bfloat16 h = __float2bfloat16_rn(v);
    g_xhi[idx] = h;
    g_xlo[idx] = __float2bfloat16_rn(v - __bfloat162float(h));
}

// ---------------- classifier: out[N,2] = (hi+lo) @ cw + cb ------------------
__global__ void classifier_kernel(const float* __restrict__ cw,
                                  const float* __restrict__ cb,
                                  float* __restrict__ out) {
    __shared__ float wsm[HF * OUTF];
    if (threadIdx.x < HF * OUTF) wsm[threadIdx.x] = cw[threadIdx.x];
    __syncthreads();
    int w = (blockIdx.x * blockDim.x + threadIdx.x) >> 5;
    if (w >= NN) return;
    int lane = threadIdx.x & 31;
    const __nv_bfloat162* ph = reinterpret_cast<const __nv_bfloat162*>(
        g_xhi + (size_t)w * HF + lane * 4);
    const __nv_bfloat162* pl = reinterpret_cast<const __nv_bfloat162*>(
        g_xlo + (size_t)w * HF + lane * 4);
    __nv_bfloat162 h0 = ph[0], h1 = ph[1], l0 = pl[0], l1 = pl[1];
    float vx = __bfloat162float(h0.x) + __bfloat162float(l0.x);
    float vy = __bfloat162float(h0.y) + __bfloat162float(l0.y);
    float vz = __bfloat162float(h1.x) + __bfloat162float(l1.x);
    float vw = __bfloat162float(h1.y) + __bfloat162float(l1.y);
    int c = lane * 4;
    float o0 = vx * wsm[(c + 0) * 2]     + vy * wsm[(c + 1) * 2]
             + vz * wsm[(c + 2) * 2]     + vw * wsm[(c + 3) * 2];
    float o1 = vx * wsm[(c + 0) * 2 + 1] + vy * wsm[(c + 1) * 2 + 1]
             + vz * wsm[(c + 2) * 2 + 1] + vw * wsm[(c + 3) * 2 + 1];
#pragma unroll
    for (int off = 16; off > 0; off >>= 1) {
        o0 += __shfl_down_sync(0xFFFFFFFFu, o0, off);
        o1 += __shfl_down_sync(0xFFFFFFFFu, o1, off);
    }
    if (lane == 0) {
        out[(size_t)w * 2 + 0] = o0 + cb[0];
        out[(size_t)w * 2 + 1] = o1 + cb[1];
    }
}

// ================================ launch =====================================
extern "C" void kernel_launch(void* const* d_in, const int* in_sizes, int n_in,
                              void* d_out, int out_size) {
    const float* x    = (const float*)d_in[0];
    const int*   ei   = (const int*)d_in[1];
    const int*   et   = (const int*)d_in[2];
    const float* w1   = (const float*)d_in[3];
    const float* r1   = (const float*)d_in[4];
    const float* b1   = (const float*)d_in[5];
    const float* g1   = (const float*)d_in[6];
    const float* be1  = (const float*)d_in[7];
    const float* w2   = (const float*)d_in[8];
    const float* r2   = (const float*)d_in[9];
    const float* b2   = (const float*)d_in[10];
    const float* g2   = (const float*)d_in[11];
    const float* be2  = (const float*)d_in[12];
    const float* cw   = (const float*)d_in[13];
    const float* cb   = (const float*)d_in[14];
    float* out = (float*)d_out;

    cudaFuncSetAttribute(gemm_tc_kernel,
                         cudaFuncAttributeMaxDynamicSharedMemorySize, SMEM_BYTES);

    int scatter_blocks  = (BINS * 32 + 255) / 256;   // warp per bin
    int bn_apply_blocks = (NN * HF + 255) / 256;
    int cls_blocks      = (NN * 32 + 255) / 256;
    int splitx_blocks   = (NN * HF + 255) / 256;
    int splitw_blocks   = (9 * 16384 + 255) / 256;
    int edge_blocks     = (EE + 255) / 256;

    // ncu captures the 4th kernel launch -> GEMM stays in slot 4.
    split_w_kernel<<<splitw_blocks, 256>>>(w1, r1);            // 1
    split_x_kernel<<<splitx_blocks, 256>>>(x);                 // 2
    zero_prep_kernel<<<(BINS + 255) / 256, 256>>>();           // 3
    gemm_tc_kernel<<<GEMM_TILES, 256, SMEM_BYTES>>>(b1);       // 4 <- profiled
    deg_hist_kernel<<<edge_blocks, 256>>>(ei, et);             // 5
    scan1_kernel<<<SCAN_BLOCKS, 256>>>();                      // 6
    scan3_kernel<<<SCAN_BLOCKS, 256>>>();                      // 7
    place_kernel<<<edge_blocks, 256>>>(ei, et);                // 8
    scatter_kernel<<<scatter_blocks, 256>>>();                 // 9
    bn_stats_kernel<<<256, 256>>>();                           // 10
    bn_apply_kernel<<<bn_apply_blocks, 256>>>(g1, be1);        // 11

    // ---- layer 2 (degree + sorted edges reused) ----
    zero_sums_kernel<<<1, 128>>>();
    split_w_kernel<<<splitw_blocks, 256>>>(w2, r2);
    gemm_tc_kernel<<<GEMM_TILES, 256, SMEM_BYTES>>>(b2);
    scatter_kernel<<<scatter_blocks, 256>>>();
    bn_stats_kernel<<<256, 256>>>();
    bn_apply_kernel<<<bn_apply_blocks, 256>>>(g2, be2);

    // ---- classifier ----
    classifier_kernel<<<cls_blocks, 256>>>(cw, cb, out);
}